// round 1
// baseline (speedup 1.0000x reference)
#include <cuda_runtime.h>
#include <math.h>

#define NN   50000
#define EE   400000
#define EP   450000   // edges + self loops
#define CIN  128
#define HID  64
#define HEADS 8
#define HC   512      // HEADS*HID
#define OUTD 3

// ---------------- scratch (device globals, no allocation) ----------------
__device__ float g_ln[NN * HC];
__device__ float g_hw[NN * HC];
__device__ float g_agg[NN * HC];
__device__ float g_h[NN * HC];
__device__ float g_alsrc[NN * HEADS];
__device__ float g_aldst[NN * HEADS];
__device__ float g_m[NN * HEADS];
__device__ float g_s[NN * HEADS];
__device__ float g_alpha[EP * HEADS];
__device__ float g_res[NN * OUTD];

// ---------------- helpers ----------------
__device__ __forceinline__ void atomicMaxF(float* addr, float v) {
    if (v >= 0.0f) atomicMax((int*)addr, __float_as_int(v));
    else           atomicMin((unsigned int*)addr, __float_as_uint(v));
}

// ---------------- LayerNorm: one block (128 thr) per row ----------------
__global__ void ln_kernel(const float* __restrict__ x, const float* __restrict__ g,
                          const float* __restrict__ b, float* __restrict__ out, int ci) {
    int n = blockIdx.x;
    const float* row = x + (size_t)n * ci;
    float s1 = 0.f, s2 = 0.f;
    for (int k = threadIdx.x; k < ci; k += 128) {
        float v = row[k];
        s1 += v; s2 += v * v;
    }
    __shared__ float sh1[4], sh2[4];
    for (int o = 16; o > 0; o >>= 1) {
        s1 += __shfl_down_sync(0xffffffffu, s1, o);
        s2 += __shfl_down_sync(0xffffffffu, s2, o);
    }
    int w = threadIdx.x >> 5, l = threadIdx.x & 31;
    if (l == 0) { sh1[w] = s1; sh2[w] = s2; }
    __syncthreads();
    if (threadIdx.x == 0) {
        float a = 0.f, c = 0.f;
        for (int i = 0; i < 4; i++) { a += sh1[i]; c += sh2[i]; }
        sh1[0] = a; sh2[0] = c;
    }
    __syncthreads();
    float inv = 1.0f / (float)ci;
    float mean = sh1[0] * inv;
    float var  = sh2[0] * inv - mean * mean;
    float rstd = rsqrtf(var + 1e-6f);
    float* orow = out + (size_t)n * ci;
    for (int k = threadIdx.x; k < ci; k += 128)
        orow[k] = (row[k] - mean) * rstd * g[k] + b[k];
}

// ---------------- GEMM: C[M,Nc] = A[M,K] * B[Nc,K]^T (both K-major) ----------------
// 64x64 tile, BK=16, 256 threads, 4x4 per thread. Nc multiple of 64, K multiple of 16.
__global__ void gemm_kernel(const float* __restrict__ A, const float* __restrict__ B,
                            float* __restrict__ C, int M, int K, int Nc) {
    __shared__ float As[16][64];
    __shared__ float Bs[16][64];
    int tid = threadIdx.x;
    int ty = tid >> 4, tx = tid & 15;
    int rowBase = blockIdx.y * 64;
    int colBase = blockIdx.x * 64;
    int lr = tid >> 2;           // 0..63
    int lc = (tid & 3) * 4;      // 0,4,8,12
    float acc[4][4];
    #pragma unroll
    for (int i = 0; i < 4; i++)
        #pragma unroll
        for (int j = 0; j < 4; j++) acc[i][j] = 0.f;

    for (int k0 = 0; k0 < K; k0 += 16) {
        int ar = rowBase + lr;
        float4 av = make_float4(0.f, 0.f, 0.f, 0.f);
        if (ar < M) av = *(const float4*)(A + (size_t)ar * K + k0 + lc);
        As[lc + 0][lr] = av.x; As[lc + 1][lr] = av.y;
        As[lc + 2][lr] = av.z; As[lc + 3][lr] = av.w;
        int br = colBase + lr;   // always < Nc (Nc multiple of 64)
        float4 bv = *(const float4*)(B + (size_t)br * K + k0 + lc);
        Bs[lc + 0][lr] = bv.x; Bs[lc + 1][lr] = bv.y;
        Bs[lc + 2][lr] = bv.z; Bs[lc + 3][lr] = bv.w;
        __syncthreads();
        #pragma unroll
        for (int k = 0; k < 16; k++) {
            float4 ra = *(const float4*)&As[k][ty * 4];
            float4 rb = *(const float4*)&Bs[k][tx * 4];
            float a0 = ra.x, a1 = ra.y, a2 = ra.z, a3 = ra.w;
            float b0 = rb.x, b1 = rb.y, b2 = rb.z, b3 = rb.w;
            acc[0][0] += a0 * b0; acc[0][1] += a0 * b1; acc[0][2] += a0 * b2; acc[0][3] += a0 * b3;
            acc[1][0] += a1 * b0; acc[1][1] += a1 * b1; acc[1][2] += a1 * b2; acc[1][3] += a1 * b3;
            acc[2][0] += a2 * b0; acc[2][1] += a2 * b1; acc[2][2] += a2 * b2; acc[2][3] += a2 * b3;
            acc[3][0] += a3 * b0; acc[3][1] += a3 * b1; acc[3][2] += a3 * b2; acc[3][3] += a3 * b3;
        }
        __syncthreads();
    }
    #pragma unroll
    for (int i = 0; i < 4; i++) {
        int r = rowBase + ty * 4 + i;
        if (r < M) {
            float4 v = make_float4(acc[i][0], acc[i][1], acc[i][2], acc[i][3]);
            *(float4*)(C + (size_t)r * Nc + colBase + tx * 4) = v;
        }
    }
}

// ---------------- attention logits: one warp per (n,h), dot over 64 ch ----------------
__global__ void attn_kernel(const float* __restrict__ hw, const float* __restrict__ asr,
                            const float* __restrict__ adt,
                            float* __restrict__ alsrc, float* __restrict__ aldst) {
    int item = blockIdx.x * 8 + (threadIdx.x >> 5);  // n*HEADS + h
    if (item >= NN * HEADS) return;
    int lane = threadIdx.x & 31;
    int h = item & (HEADS - 1);
    const float2* v  = (const float2*)(hw + (size_t)item * 64);
    const float2* w1 = (const float2*)(asr + h * 64);
    const float2* w2 = (const float2*)(adt + h * 64);
    float2 vv = v[lane], a1 = w1[lane], a2 = w2[lane];
    float s1 = vv.x * a1.x + vv.y * a1.y;
    float s2 = vv.x * a2.x + vv.y * a2.y;
    for (int o = 16; o > 0; o >>= 1) {
        s1 += __shfl_xor_sync(0xffffffffu, s1, o);
        s2 += __shfl_xor_sync(0xffffffffu, s2, o);
    }
    if (lane == 0) { alsrc[item] = s1; aldst[item] = s2; }
}

// ---------------- per-layer state init ----------------
__global__ void init_kernel(float* m, float* s, float* agg, int nms, int nagg) {
    int idx = blockIdx.x * blockDim.x + threadIdx.x;
    if (idx < nagg) agg[idx] = 0.f;
    if (idx < nms) { m[idx] = __int_as_float(0xff800000); s[idx] = 0.f; }
}

// ---------------- edge passes ----------------
__global__ void edge_max_kernel(const int* __restrict__ ei, const float* __restrict__ alsrc,
                                const float* __restrict__ aldst, float* m, float* alpha, int H) {
    int idx = blockIdx.x * blockDim.x + threadIdx.x;
    if (idx >= EP * H) return;
    int e = idx / H, h = idx - e * H;
    int src, dst;
    if (e < EE) { src = ei[e]; dst = ei[EE + e]; } else { src = dst = e - EE; }
    float v = alsrc[src * H + h] + aldst[dst * H + h];
    v = v > 0.f ? v : 0.2f * v;
    alpha[idx] = v;
    atomicMaxF(&m[dst * H + h], v);
}

__global__ void edge_exp_kernel(const int* __restrict__ ei, const float* __restrict__ m,
                                float* s, float* alpha, int H) {
    int idx = blockIdx.x * blockDim.x + threadIdx.x;
    if (idx >= EP * H) return;
    int e = idx / H, h = idx - e * H;
    int dst = (e < EE) ? ei[EE + e] : e - EE;
    float ex = expf(alpha[idx] - m[dst * H + h]);
    alpha[idx] = ex;
    atomicAdd(&s[dst * H + h], ex);
}

__global__ void edge_norm_kernel(const int* __restrict__ ei, const float* __restrict__ s,
                                 float* alpha, int H) {
    int idx = blockIdx.x * blockDim.x + threadIdx.x;
    if (idx >= EP * H) return;
    int e = idx / H, h = idx - e * H;
    int dst = (e < EE) ? ei[EE + e] : e - EE;
    alpha[idx] = alpha[idx] / s[dst * H + h];
}

// ---------------- message passing (H=8, C=64): float4 granularity ----------------
__global__ void msg8_kernel(const int* __restrict__ ei, const float* __restrict__ alpha,
                            const float* __restrict__ hw, float* agg) {
    int idx = blockIdx.x * blockDim.x + threadIdx.x;   // EP*128 threads
    if (idx >= EP * 128) return;
    int e = idx >> 7;
    int r = idx & 127;          // float4 index within row
    int h = r >> 4;
    int src, dst;
    if (e < EE) { src = ei[e]; dst = ei[EE + e]; } else { src = dst = e - EE; }
    float a = alpha[e * 8 + h];
    float4 v = *(const float4*)(hw + ((size_t)src << 9) + (r << 2));
    float* o = agg + ((size_t)dst << 9) + (r << 2);
    atomicAdd(o + 0, v.x * a);
    atomicAdd(o + 1, v.y * a);
    atomicAdd(o + 2, v.z * a);
    atomicAdd(o + 3, v.w * a);
}

// ---------------- epilogue: bias + exact gelu + optional residual ----------------
__global__ void epi_kernel(const float* __restrict__ agg, const float* __restrict__ bias,
                           float* h, int addRes) {
    int idx = blockIdx.x * blockDim.x + threadIdx.x;
    if (idx >= NN * HC) return;
    int j = idx & (HC - 1);
    float v = agg[idx] + bias[j];
    v = 0.5f * v * (1.0f + erff(v * 0.70710678118654752f));
    if (addRes) v += h[idx];
    h[idx] = v;
}

// ---------------- layer 3: tiny GEMM [N,512]x[3,512]^T + attn logits ----------------
__global__ void gemm3_kernel(const float* __restrict__ ln, const float* __restrict__ W,
                             const float* __restrict__ asr, const float* __restrict__ adt,
                             float* hw3, float* alsrc, float* aldst) {
    int n = blockIdx.x, t = threadIdx.x;
    const float* row = ln + (size_t)n * 512;
    float p0 = 0.f, p1 = 0.f, p2 = 0.f;
    for (int k = t; k < 512; k += 128) {
        float a = row[k];
        p0 += a * W[k];
        p1 += a * W[512 + k];
        p2 += a * W[1024 + k];
    }
    __shared__ float sh[3][4];
    for (int o = 16; o > 0; o >>= 1) {
        p0 += __shfl_down_sync(0xffffffffu, p0, o);
        p1 += __shfl_down_sync(0xffffffffu, p1, o);
        p2 += __shfl_down_sync(0xffffffffu, p2, o);
    }
    int w = t >> 5, l = t & 31;
    if (l == 0) { sh[0][w] = p0; sh[1][w] = p1; sh[2][w] = p2; }
    __syncthreads();
    if (t == 0) {
        float v0 = sh[0][0] + sh[0][1] + sh[0][2] + sh[0][3];
        float v1 = sh[1][0] + sh[1][1] + sh[1][2] + sh[1][3];
        float v2 = sh[2][0] + sh[2][1] + sh[2][2] + sh[2][3];
        hw3[n * 3 + 0] = v0; hw3[n * 3 + 1] = v1; hw3[n * 3 + 2] = v2;
        alsrc[n] = v0 * asr[0] + v1 * asr[1] + v2 * asr[2];
        aldst[n] = v0 * adt[0] + v1 * adt[1] + v2 * adt[2];
    }
}

__global__ void msg3_kernel(const int* __restrict__ ei, const float* __restrict__ alpha,
                            const float* __restrict__ hw3, float* agg) {
    int e = blockIdx.x * blockDim.x + threadIdx.x;
    if (e >= EP) return;
    int src, dst;
    if (e < EE) { src = ei[e]; dst = ei[EE + e]; } else { src = dst = e - EE; }
    float a = alpha[e];
    atomicAdd(&agg[dst * 3 + 0], hw3[src * 3 + 0] * a);
    atomicAdd(&agg[dst * 3 + 1], hw3[src * 3 + 1] * a);
    atomicAdd(&agg[dst * 3 + 2], hw3[src * 3 + 2] * a);
}

// ---------------- input residual: res = x @ res_W^T + res_b ----------------
__global__ void resid_kernel(const float* __restrict__ x, const float* __restrict__ rw,
                             const float* __restrict__ rb, float* res) {
    int n = blockIdx.x, t = threadIdx.x;   // 128 threads, ci=128
    float a = x[(size_t)n * 128 + t];
    float p0 = a * rw[t], p1 = a * rw[128 + t], p2 = a * rw[256 + t];
    __shared__ float sh[3][4];
    for (int o = 16; o > 0; o >>= 1) {
        p0 += __shfl_down_sync(0xffffffffu, p0, o);
        p1 += __shfl_down_sync(0xffffffffu, p1, o);
        p2 += __shfl_down_sync(0xffffffffu, p2, o);
    }
    int w = t >> 5, l = t & 31;
    if (l == 0) { sh[0][w] = p0; sh[1][w] = p1; sh[2][w] = p2; }
    __syncthreads();
    if (t == 0) {
        res[n * 3 + 0] = sh[0][0] + sh[0][1] + sh[0][2] + sh[0][3] + rb[0];
        res[n * 3 + 1] = sh[1][0] + sh[1][1] + sh[1][2] + sh[1][3] + rb[1];
        res[n * 3 + 2] = sh[2][0] + sh[2][1] + sh[2][2] + sh[2][3] + rb[2];
    }
}

__global__ void final_kernel(const float* __restrict__ agg, const float* __restrict__ b3,
                             const float* __restrict__ res, float* __restrict__ out) {
    int idx = blockIdx.x * blockDim.x + threadIdx.x;
    if (idx >= NN * 3) return;
    out[idx] = agg[idx] + b3[idx % 3] + res[idx];
}

// ---------------- launch ----------------
extern "C" void kernel_launch(void* const* d_in, const int* in_sizes, int n_in,
                              void* d_out, int out_size) {
    const float* x    = (const float*)d_in[0];
    const int*   ei   = (const int*)d_in[1];
    const float* resW = (const float*)d_in[2];
    const float* resb = (const float*)d_in[3];

    // per-layer params: base 4 + 6*l : ln_g, ln_b, W, asr, adt, bias
    const float* lng[4];  const float* lnb[4];
    const float* Wl[4];   const float* asr[4];
    const float* adt[4];  const float* bl[4];
    for (int l = 0; l < 4; l++) {
        int base = 4 + 6 * l;
        lng[l] = (const float*)d_in[base + 0];
        lnb[l] = (const float*)d_in[base + 1];
        Wl[l]  = (const float*)d_in[base + 2];
        asr[l] = (const float*)d_in[base + 3];
        adt[l] = (const float*)d_in[base + 4];
        bl[l]  = (const float*)d_in[base + 5];
    }

    float *ln_, *hw_, *agg_, *h_, *alsrc_, *aldst_, *m_, *s_, *alpha_, *res_;
    cudaGetSymbolAddress((void**)&ln_,    g_ln);
    cudaGetSymbolAddress((void**)&hw_,    g_hw);
    cudaGetSymbolAddress((void**)&agg_,   g_agg);
    cudaGetSymbolAddress((void**)&h_,     g_h);
    cudaGetSymbolAddress((void**)&alsrc_, g_alsrc);
    cudaGetSymbolAddress((void**)&aldst_, g_aldst);
    cudaGetSymbolAddress((void**)&m_,     g_m);
    cudaGetSymbolAddress((void**)&s_,     g_s);
    cudaGetSymbolAddress((void**)&alpha_, g_alpha);
    cudaGetSymbolAddress((void**)&res_,   g_res);

    resid_kernel<<<NN, 128>>>(x, resW, resb, res_);

    for (int l = 0; l < 3; l++) {
        const float* hin = (l == 0) ? x : h_;
        int ci = (l == 0) ? CIN : HC;
        ln_kernel<<<NN, 128>>>(hin, lng[l], lnb[l], ln_, ci);
        gemm_kernel<<<dim3(HC / 64, (NN + 63) / 64), 256>>>(ln_, Wl[l], hw_, NN, ci, HC);
        attn_kernel<<<NN, 256>>>(hw_, asr[l], adt[l], alsrc_, aldst_);
        init_kernel<<<(NN * HC + 255) / 256, 256>>>(m_, s_, agg_, NN * HEADS, NN * HC);
        edge_max_kernel<<<(EP * HEADS + 255) / 256, 256>>>(ei, alsrc_, aldst_, m_, alpha_, HEADS);
        edge_exp_kernel<<<(EP * HEADS + 255) / 256, 256>>>(ei, m_, s_, alpha_, HEADS);
        edge_norm_kernel<<<(EP * HEADS + 255) / 256, 256>>>(ei, s_, alpha_, HEADS);
        msg8_kernel<<<(EP * 128 + 255) / 256, 256>>>(ei, alpha_, hw_, agg_);
        epi_kernel<<<(NN * HC + 255) / 256, 256>>>(agg_, bl[l], h_, l > 0 ? 1 : 0);
    }

    // layer 3 (heads=1, co=3, no concat, no gelu)
    ln_kernel<<<NN, 128>>>(h_, lng[3], lnb[3], ln_, HC);
    gemm3_kernel<<<NN, 128>>>(ln_, Wl[3], asr[3], adt[3], hw_, alsrc_, aldst_);
    init_kernel<<<(NN * 3 + 255) / 256, 256>>>(m_, s_, agg_, NN, NN * 3);
    edge_max_kernel<<<(EP + 255) / 256, 256>>>(ei, alsrc_, aldst_, m_, alpha_, 1);
    edge_exp_kernel<<<(EP + 255) / 256, 256>>>(ei, m_, s_, alpha_, 1);
    edge_norm_kernel<<<(EP + 255) / 256, 256>>>(ei, s_, alpha_, 1);
    msg3_kernel<<<(EP + 255) / 256, 256>>>(ei, alpha_, hw_, agg_);
    final_kernel<<<(NN * 3 + 255) / 256, 256>>>(agg_, bl[3], res_, (float*)d_out);
}

// round 2
// speedup vs baseline: 1.2251x; 1.2251x over previous
#include <cuda_runtime.h>
#include <mma.h>
#include <math.h>

using namespace nvcuda;

#define NN   50000
#define NP   50048    // padded to multiple of 128 for GEMM tile stores
#define EE   400000
#define EP   450000   // edges + self loops
#define CIN  128
#define HID  64
#define HEADS 8
#define HC   512      // HEADS*HID
#define OUTD 3

// ---------------- scratch (device globals, no allocation) ----------------
__device__ float g_ln[NP * HC];
__device__ float g_hw[NP * HC];
__device__ float g_agg[NN * HC];
__device__ float g_h[NN * HC];
__device__ float g_alsrc[NN * HEADS];
__device__ float g_aldst[NN * HEADS];
__device__ float g_m[NN * HEADS];
__device__ float g_s[NN * HEADS];
__device__ float g_alpha[EP * HEADS];
__device__ float g_res[NN * OUTD];

// ---------------- helpers ----------------
__device__ __forceinline__ void atomicMaxF(float* addr, float v) {
    if (v >= 0.0f) atomicMax((int*)addr, __float_as_int(v));
    else           atomicMin((unsigned int*)addr, __float_as_uint(v));
}

// ---------------- LayerNorm: one block (128 thr) per row ----------------
__global__ void ln_kernel(const float* __restrict__ x, const float* __restrict__ g,
                          const float* __restrict__ b, float* __restrict__ out, int ci) {
    int n = blockIdx.x;
    const float* row = x + (size_t)n * ci;
    float s1 = 0.f, s2 = 0.f;
    for (int k = threadIdx.x; k < ci; k += 128) {
        float v = row[k];
        s1 += v; s2 += v * v;
    }
    __shared__ float sh1[4], sh2[4];
    for (int o = 16; o > 0; o >>= 1) {
        s1 += __shfl_down_sync(0xffffffffu, s1, o);
        s2 += __shfl_down_sync(0xffffffffu, s2, o);
    }
    int w = threadIdx.x >> 5, l = threadIdx.x & 31;
    if (l == 0) { sh1[w] = s1; sh2[w] = s2; }
    __syncthreads();
    if (threadIdx.x == 0) {
        float a = 0.f, c = 0.f;
        for (int i = 0; i < 4; i++) { a += sh1[i]; c += sh2[i]; }
        sh1[0] = a; sh2[0] = c;
    }
    __syncthreads();
    float inv = 1.0f / (float)ci;
    float mean = sh1[0] * inv;
    float var  = sh2[0] * inv - mean * mean;
    float rstd = rsqrtf(var + 1e-6f);
    float* orow = out + (size_t)n * ci;
    for (int k = threadIdx.x; k < ci; k += 128)
        orow[k] = (row[k] - mean) * rstd * g[k] + b[k];
}

// ---------------- tf32 tensor-core GEMM: C[M,Nc] = A[M,K] * B[Nc,K]^T ----------------
// Block tile 128x64, 256 threads = 8 warps (4x2), each warp 32x32 via 2x2 wmma m16n16k8.
// A row-major [M,K] (M padded to 128 in the output buffer), B K-major [Nc,K].
#define BM 128
#define BN 64
#define BK 16
#define SPAD 8
#define SLD (BK + SPAD)   // 24 floats

__global__ void gemm_tf32(const float* __restrict__ A, const float* __restrict__ B,
                          float* __restrict__ C, int M, int K, int Nc) {
    __shared__ __align__(16) float As[BM][SLD];
    __shared__ __align__(16) float Bs[BN][SLD];
    int tid = threadIdx.x;
    int warp = tid >> 5;
    int wm = warp >> 1;      // 0..3
    int wn = warp & 1;       // 0..1
    int rowBase = blockIdx.y * BM;
    int colBase = blockIdx.x * BN;

    wmma::fragment<wmma::accumulator, 16, 16, 8, float> acc[2][2];
    #pragma unroll
    for (int i = 0; i < 2; i++)
        #pragma unroll
        for (int j = 0; j < 2; j++) wmma::fill_fragment(acc[i][j], 0.f);

    for (int k0 = 0; k0 < K; k0 += BK) {
        // load A tile: 128x16 = 512 float4, 2 per thread
        #pragma unroll
        for (int i = 0; i < 2; i++) {
            int idx = tid + i * 256;
            int r = idx >> 2;
            int c = (idx & 3) * 4;
            int gr = rowBase + r;
            float4 v = make_float4(0.f, 0.f, 0.f, 0.f);
            if (gr < M) v = *(const float4*)(A + (size_t)gr * K + k0 + c);
            As[r][c + 0] = wmma::__float_to_tf32(v.x);
            As[r][c + 1] = wmma::__float_to_tf32(v.y);
            As[r][c + 2] = wmma::__float_to_tf32(v.z);
            As[r][c + 3] = wmma::__float_to_tf32(v.w);
        }
        // load B tile: 64x16 = 256 float4, 1 per thread
        {
            int r = tid >> 2;
            int c = (tid & 3) * 4;
            float4 v = *(const float4*)(B + (size_t)(colBase + r) * K + k0 + c);
            Bs[r][c + 0] = wmma::__float_to_tf32(v.x);
            Bs[r][c + 1] = wmma::__float_to_tf32(v.y);
            Bs[r][c + 2] = wmma::__float_to_tf32(v.z);
            Bs[r][c + 3] = wmma::__float_to_tf32(v.w);
        }
        __syncthreads();
        #pragma unroll
        for (int kk = 0; kk < BK; kk += 8) {
            wmma::fragment<wmma::matrix_a, 16, 16, 8, wmma::precision::tf32, wmma::row_major> af[2];
            wmma::fragment<wmma::matrix_b, 16, 16, 8, wmma::precision::tf32, wmma::col_major> bf[2];
            #pragma unroll
            for (int i = 0; i < 2; i++)
                wmma::load_matrix_sync(af[i], &As[wm * 32 + i * 16][kk], SLD);
            #pragma unroll
            for (int j = 0; j < 2; j++)
                wmma::load_matrix_sync(bf[j], &Bs[wn * 32 + j * 16][kk], SLD);
            #pragma unroll
            for (int i = 0; i < 2; i++)
                #pragma unroll
                for (int j = 0; j < 2; j++)
                    wmma::mma_sync(acc[i][j], af[i], bf[j], acc[i][j]);
        }
        __syncthreads();
    }
    // store (C buffer is padded to 128-row multiple, unguarded)
    #pragma unroll
    for (int i = 0; i < 2; i++)
        #pragma unroll
        for (int j = 0; j < 2; j++) {
            int r = rowBase + wm * 32 + i * 16;
            int c = colBase + wn * 32 + j * 16;
            wmma::store_matrix_sync(C + (size_t)r * Nc + c, acc[i][j], Nc, wmma::mem_row_major);
        }
}

// ---------------- attention logits: one warp per (n,h), dot over 64 ch ----------------
__global__ void attn_kernel(const float* __restrict__ hw, const float* __restrict__ asr,
                            const float* __restrict__ adt,
                            float* __restrict__ alsrc, float* __restrict__ aldst) {
    int item = blockIdx.x * 8 + (threadIdx.x >> 5);  // n*HEADS + h
    if (item >= NN * HEADS) return;
    int lane = threadIdx.x & 31;
    int h = item & (HEADS - 1);
    const float2* v  = (const float2*)(hw + (size_t)item * 64);
    const float2* w1 = (const float2*)(asr + h * 64);
    const float2* w2 = (const float2*)(adt + h * 64);
    float2 vv = v[lane], a1 = w1[lane], a2 = w2[lane];
    float s1 = vv.x * a1.x + vv.y * a1.y;
    float s2 = vv.x * a2.x + vv.y * a2.y;
    for (int o = 16; o > 0; o >>= 1) {
        s1 += __shfl_xor_sync(0xffffffffu, s1, o);
        s2 += __shfl_xor_sync(0xffffffffu, s2, o);
    }
    if (lane == 0) { alsrc[item] = s1; aldst[item] = s2; }
}

// ---------------- per-layer state init ----------------
__global__ void init_kernel(float* m, float* s, float* agg, int nms, int nagg) {
    int idx = blockIdx.x * blockDim.x + threadIdx.x;
    if (idx < nagg) agg[idx] = 0.f;
    if (idx < nms) { m[idx] = __int_as_float(0xff800000); s[idx] = 0.f; }
}

// ---------------- edge passes ----------------
__global__ void edge_max_kernel(const int* __restrict__ ei, const float* __restrict__ alsrc,
                                const float* __restrict__ aldst, float* m, float* alpha, int H) {
    int idx = blockIdx.x * blockDim.x + threadIdx.x;
    if (idx >= EP * H) return;
    int e = idx / H, h = idx - e * H;
    int src, dst;
    if (e < EE) { src = ei[e]; dst = ei[EE + e]; } else { src = dst = e - EE; }
    float v = alsrc[src * H + h] + aldst[dst * H + h];
    v = v > 0.f ? v : 0.2f * v;
    alpha[idx] = v;
    atomicMaxF(&m[dst * H + h], v);
}

__global__ void edge_exp_kernel(const int* __restrict__ ei, const float* __restrict__ m,
                                float* s, float* alpha, int H) {
    int idx = blockIdx.x * blockDim.x + threadIdx.x;
    if (idx >= EP * H) return;
    int e = idx / H, h = idx - e * H;
    int dst = (e < EE) ? ei[EE + e] : e - EE;
    float ex = expf(alpha[idx] - m[dst * H + h]);
    alpha[idx] = ex;
    atomicAdd(&s[dst * H + h], ex);
}

__global__ void edge_norm_kernel(const int* __restrict__ ei, const float* __restrict__ s,
                                 float* alpha, int H) {
    int idx = blockIdx.x * blockDim.x + threadIdx.x;
    if (idx >= EP * H) return;
    int e = idx / H, h = idx - e * H;
    int dst = (e < EE) ? ei[EE + e] : e - EE;
    alpha[idx] = alpha[idx] / s[dst * H + h];
}

// ---------------- message passing (H=8, C=64): float4 granularity ----------------
__global__ void msg8_kernel(const int* __restrict__ ei, const float* __restrict__ alpha,
                            const float* __restrict__ hw, float* agg) {
    int idx = blockIdx.x * blockDim.x + threadIdx.x;   // EP*128 threads
    if (idx >= EP * 128) return;
    int e = idx >> 7;
    int r = idx & 127;          // float4 index within row
    int h = r >> 4;
    int src, dst;
    if (e < EE) { src = ei[e]; dst = ei[EE + e]; } else { src = dst = e - EE; }
    float a = alpha[e * 8 + h];
    float4 v = *(const float4*)(hw + ((size_t)src << 9) + (r << 2));
    float* o = agg + ((size_t)dst << 9) + (r << 2);
    atomicAdd(o + 0, v.x * a);
    atomicAdd(o + 1, v.y * a);
    atomicAdd(o + 2, v.z * a);
    atomicAdd(o + 3, v.w * a);
}

// ---------------- epilogue: bias + exact gelu + optional residual ----------------
__global__ void epi_kernel(const float* __restrict__ agg, const float* __restrict__ bias,
                           float* h, int addRes) {
    int idx = blockIdx.x * blockDim.x + threadIdx.x;
    if (idx >= NN * HC) return;
    int j = idx & (HC - 1);
    float v = agg[idx] + bias[j];
    v = 0.5f * v * (1.0f + erff(v * 0.70710678118654752f));
    if (addRes) v += h[idx];
    h[idx] = v;
}

// ---------------- layer 3: tiny GEMM [N,512]x[3,512]^T + attn logits ----------------
__global__ void gemm3_kernel(const float* __restrict__ ln, const float* __restrict__ W,
                             const float* __restrict__ asr, const float* __restrict__ adt,
                             float* hw3, float* alsrc, float* aldst) {
    int n = blockIdx.x, t = threadIdx.x;
    const float* row = ln + (size_t)n * 512;
    float p0 = 0.f, p1 = 0.f, p2 = 0.f;
    for (int k = t; k < 512; k += 128) {
        float a = row[k];
        p0 += a * W[k];
        p1 += a * W[512 + k];
        p2 += a * W[1024 + k];
    }
    __shared__ float sh[3][4];
    for (int o = 16; o > 0; o >>= 1) {
        p0 += __shfl_down_sync(0xffffffffu, p0, o);
        p1 += __shfl_down_sync(0xffffffffu, p1, o);
        p2 += __shfl_down_sync(0xffffffffu, p2, o);
    }
    int w = t >> 5, l = t & 31;
    if (l == 0) { sh[0][w] = p0; sh[1][w] = p1; sh[2][w] = p2; }
    __syncthreads();
    if (t == 0) {
        float v0 = sh[0][0] + sh[0][1] + sh[0][2] + sh[0][3];
        float v1 = sh[1][0] + sh[1][1] + sh[1][2] + sh[1][3];
        float v2 = sh[2][0] + sh[2][1] + sh[2][2] + sh[2][3];
        hw3[n * 3 + 0] = v0; hw3[n * 3 + 1] = v1; hw3[n * 3 + 2] = v2;
        alsrc[n] = v0 * asr[0] + v1 * asr[1] + v2 * asr[2];
        aldst[n] = v0 * adt[0] + v1 * adt[1] + v2 * adt[2];
    }
}

__global__ void msg3_kernel(const int* __restrict__ ei, const float* __restrict__ alpha,
                            const float* __restrict__ hw3, float* agg) {
    int e = blockIdx.x * blockDim.x + threadIdx.x;
    if (e >= EP) return;
    int src, dst;
    if (e < EE) { src = ei[e]; dst = ei[EE + e]; } else { src = dst = e - EE; }
    float a = alpha[e];
    atomicAdd(&agg[dst * 3 + 0], hw3[src * 3 + 0] * a);
    atomicAdd(&agg[dst * 3 + 1], hw3[src * 3 + 1] * a);
    atomicAdd(&agg[dst * 3 + 2], hw3[src * 3 + 2] * a);
}

// ---------------- input residual: res = x @ res_W^T + res_b ----------------
__global__ void resid_kernel(const float* __restrict__ x, const float* __restrict__ rw,
                             const float* __restrict__ rb, float* res) {
    int n = blockIdx.x, t = threadIdx.x;   // 128 threads, ci=128
    float a = x[(size_t)n * 128 + t];
    float p0 = a * rw[t], p1 = a * rw[128 + t], p2 = a * rw[256 + t];
    __shared__ float sh[3][4];
    for (int o = 16; o > 0; o >>= 1) {
        p0 += __shfl_down_sync(0xffffffffu, p0, o);
        p1 += __shfl_down_sync(0xffffffffu, p1, o);
        p2 += __shfl_down_sync(0xffffffffu, p2, o);
    }
    int w = t >> 5, l = t & 31;
    if (l == 0) { sh[0][w] = p0; sh[1][w] = p1; sh[2][w] = p2; }
    __syncthreads();
    if (t == 0) {
        res[n * 3 + 0] = sh[0][0] + sh[0][1] + sh[0][2] + sh[0][3] + rb[0];
        res[n * 3 + 1] = sh[1][0] + sh[1][1] + sh[1][2] + sh[1][3] + rb[1];
        res[n * 3 + 2] = sh[2][0] + sh[2][1] + sh[2][2] + sh[2][3] + rb[2];
    }
}

__global__ void final_kernel(const float* __restrict__ agg, const float* __restrict__ b3,
                             const float* __restrict__ res, float* __restrict__ out) {
    int idx = blockIdx.x * blockDim.x + threadIdx.x;
    if (idx >= NN * 3) return;
    out[idx] = agg[idx] + b3[idx % 3] + res[idx];
}

// ---------------- launch ----------------
extern "C" void kernel_launch(void* const* d_in, const int* in_sizes, int n_in,
                              void* d_out, int out_size) {
    const float* x    = (const float*)d_in[0];
    const int*   ei   = (const int*)d_in[1];
    const float* resW = (const float*)d_in[2];
    const float* resb = (const float*)d_in[3];

    const float* lng[4];  const float* lnb[4];
    const float* Wl[4];   const float* asr[4];
    const float* adt[4];  const float* bl[4];
    for (int l = 0; l < 4; l++) {
        int base = 4 + 6 * l;
        lng[l] = (const float*)d_in[base + 0];
        lnb[l] = (const float*)d_in[base + 1];
        Wl[l]  = (const float*)d_in[base + 2];
        asr[l] = (const float*)d_in[base + 3];
        adt[l] = (const float*)d_in[base + 4];
        bl[l]  = (const float*)d_in[base + 5];
    }

    float *ln_, *hw_, *agg_, *h_, *alsrc_, *aldst_, *m_, *s_, *alpha_, *res_;
    cudaGetSymbolAddress((void**)&ln_,    g_ln);
    cudaGetSymbolAddress((void**)&hw_,    g_hw);
    cudaGetSymbolAddress((void**)&agg_,   g_agg);
    cudaGetSymbolAddress((void**)&h_,     g_h);
    cudaGetSymbolAddress((void**)&alsrc_, g_alsrc);
    cudaGetSymbolAddress((void**)&aldst_, g_aldst);
    cudaGetSymbolAddress((void**)&m_,     g_m);
    cudaGetSymbolAddress((void**)&s_,     g_s);
    cudaGetSymbolAddress((void**)&alpha_, g_alpha);
    cudaGetSymbolAddress((void**)&res_,   g_res);

    resid_kernel<<<NN, 128>>>(x, resW, resb, res_);

    for (int l = 0; l < 3; l++) {
        const float* hin = (l == 0) ? x : h_;
        int ci = (l == 0) ? CIN : HC;
        ln_kernel<<<NN, 128>>>(hin, lng[l], lnb[l], ln_, ci);
        gemm_tf32<<<dim3(HC / BN, NP / BM), 256>>>(ln_, Wl[l], hw_, NN, ci, HC);
        attn_kernel<<<NN, 256>>>(hw_, asr[l], adt[l], alsrc_, aldst_);
        init_kernel<<<(NN * HC + 255) / 256, 256>>>(m_, s_, agg_, NN * HEADS, NN * HC);
        edge_max_kernel<<<(EP * HEADS + 255) / 256, 256>>>(ei, alsrc_, aldst_, m_, alpha_, HEADS);
        edge_exp_kernel<<<(EP * HEADS + 255) / 256, 256>>>(ei, m_, s_, alpha_, HEADS);
        edge_norm_kernel<<<(EP * HEADS + 255) / 256, 256>>>(ei, s_, alpha_, HEADS);
        msg8_kernel<<<(EP * 128 + 255) / 256, 256>>>(ei, alpha_, hw_, agg_);
        epi_kernel<<<(NN * HC + 255) / 256, 256>>>(agg_, bl[l], h_, l > 0 ? 1 : 0);
    }

    // layer 3 (heads=1, co=3, no concat, no gelu)
    ln_kernel<<<NN, 128>>>(h_, lng[3], lnb[3], ln_, HC);
    gemm3_kernel<<<NN, 128>>>(ln_, Wl[3], asr[3], adt[3], hw_, alsrc_, aldst_);
    init_kernel<<<(NN * 3 + 255) / 256, 256>>>(m_, s_, agg_, NN, NN * 3);
    edge_max_kernel<<<(EP + 255) / 256, 256>>>(ei, alsrc_, aldst_, m_, alpha_, 1);
    edge_exp_kernel<<<(EP + 255) / 256, 256>>>(ei, m_, s_, alpha_, 1);
    edge_norm_kernel<<<(EP + 255) / 256, 256>>>(ei, s_, alpha_, 1);
    msg3_kernel<<<(EP + 255) / 256, 256>>>(ei, alpha_, hw_, agg_);
    final_kernel<<<(NN * 3 + 255) / 256, 256>>>(agg_, bl[3], res_, (float*)d_out);
}

// round 3
// speedup vs baseline: 1.4458x; 1.1801x over previous
#include <cuda_runtime.h>
#include <mma.h>
#include <math.h>

using namespace nvcuda;

#define NN   50000
#define NP   50048    // padded to multiple of 128 for GEMM tile stores
#define EE   400000
#define EP   450000   // edges + self loops
#define CIN  128
#define HID  64
#define HEADS 8
#define HC   512      // HEADS*HID
#define OUTD 3

// ---------------- scratch (device globals, no allocation) ----------------
__device__ float g_ln[NP * HC];
__device__ float g_hw[NP * HC];
__device__ float g_agg[NN * HC];
__device__ float g_h[NN * HC];
__device__ float g_alsrc[NN * HEADS];
__device__ float g_aldst[NN * HEADS];
__device__ float g_m[NN * HEADS];
__device__ float g_s[NN * HEADS];
__device__ float g_alpha[EP * HEADS];
__device__ float g_res[NN * OUTD];

// ---------------- helpers ----------------
__device__ __forceinline__ void atomicMaxF(float* addr, float v) {
    if (v >= 0.0f) atomicMax((int*)addr, __float_as_int(v));
    else           atomicMin((unsigned int*)addr, __float_as_uint(v));
}

__device__ __forceinline__ void redAddV4(float* addr, float a, float b, float c, float d) {
    asm volatile("red.global.add.v4.f32 [%0], {%1, %2, %3, %4};"
                 :: "l"(addr), "f"(a), "f"(b), "f"(c), "f"(d) : "memory");
}

// ---------------- LayerNorm: one block (128 thr) per row ----------------
__global__ void ln_kernel(const float* __restrict__ x, const float* __restrict__ g,
                          const float* __restrict__ b, float* __restrict__ out, int ci) {
    int n = blockIdx.x;
    const float* row = x + (size_t)n * ci;
    float s1 = 0.f, s2 = 0.f;
    for (int k = threadIdx.x; k < ci; k += 128) {
        float v = row[k];
        s1 += v; s2 += v * v;
    }
    __shared__ float sh1[4], sh2[4];
    for (int o = 16; o > 0; o >>= 1) {
        s1 += __shfl_down_sync(0xffffffffu, s1, o);
        s2 += __shfl_down_sync(0xffffffffu, s2, o);
    }
    int w = threadIdx.x >> 5, l = threadIdx.x & 31;
    if (l == 0) { sh1[w] = s1; sh2[w] = s2; }
    __syncthreads();
    if (threadIdx.x == 0) {
        float a = 0.f, c = 0.f;
        for (int i = 0; i < 4; i++) { a += sh1[i]; c += sh2[i]; }
        sh1[0] = a; sh2[0] = c;
    }
    __syncthreads();
    float inv = 1.0f / (float)ci;
    float mean = sh1[0] * inv;
    float var  = sh2[0] * inv - mean * mean;
    float rstd = rsqrtf(var + 1e-6f);
    float* orow = out + (size_t)n * ci;
    for (int k = threadIdx.x; k < ci; k += 128)
        orow[k] = (row[k] - mean) * rstd * g[k] + b[k];
}

// ---------------- tf32 tensor-core GEMM: C[M,Nc] = A[M,K] * B[Nc,K]^T ----------------
// Block tile 128x128, 256 threads = 8 warps (4x2), each warp 32x64 via 2x4 wmma m16n16k8.
#define BM 128
#define BN 128
#define BK 16
#define SPAD 8
#define SLD (BK + SPAD)   // 24 floats

__global__ void gemm_tf32(const float* __restrict__ A, const float* __restrict__ B,
                          float* __restrict__ C, int M, int K, int Nc) {
    __shared__ __align__(16) float As[BM][SLD];
    __shared__ __align__(16) float Bs[BN][SLD];
    int tid = threadIdx.x;
    int warp = tid >> 5;
    int wm = warp >> 1;      // 0..3 -> 32-row strip
    int wn = warp & 1;       // 0..1 -> 64-col strip
    int rowBase = blockIdx.y * BM;
    int colBase = blockIdx.x * BN;

    wmma::fragment<wmma::accumulator, 16, 16, 8, float> acc[2][4];
    #pragma unroll
    for (int i = 0; i < 2; i++)
        #pragma unroll
        for (int j = 0; j < 4; j++) wmma::fill_fragment(acc[i][j], 0.f);

    for (int k0 = 0; k0 < K; k0 += BK) {
        // A tile: 128x16 = 512 float4, 2 per thread
        #pragma unroll
        for (int i = 0; i < 2; i++) {
            int idx = tid + i * 256;
            int r = idx >> 2;
            int c = (idx & 3) * 4;
            int gr = rowBase + r;
            float4 v = make_float4(0.f, 0.f, 0.f, 0.f);
            if (gr < M) v = *(const float4*)(A + (size_t)gr * K + k0 + c);
            As[r][c + 0] = wmma::__float_to_tf32(v.x);
            As[r][c + 1] = wmma::__float_to_tf32(v.y);
            As[r][c + 2] = wmma::__float_to_tf32(v.z);
            As[r][c + 3] = wmma::__float_to_tf32(v.w);
        }
        // B tile: 128x16 = 512 float4, 2 per thread
        #pragma unroll
        for (int i = 0; i < 2; i++) {
            int idx = tid + i * 256;
            int r = idx >> 2;
            int c = (idx & 3) * 4;
            float4 v = *(const float4*)(B + (size_t)(colBase + r) * K + k0 + c);
            Bs[r][c + 0] = wmma::__float_to_tf32(v.x);
            Bs[r][c + 1] = wmma::__float_to_tf32(v.y);
            Bs[r][c + 2] = wmma::__float_to_tf32(v.z);
            Bs[r][c + 3] = wmma::__float_to_tf32(v.w);
        }
        __syncthreads();
        #pragma unroll
        for (int kk = 0; kk < BK; kk += 8) {
            wmma::fragment<wmma::matrix_a, 16, 16, 8, wmma::precision::tf32, wmma::row_major> af[2];
            wmma::fragment<wmma::matrix_b, 16, 16, 8, wmma::precision::tf32, wmma::col_major> bf[4];
            #pragma unroll
            for (int i = 0; i < 2; i++)
                wmma::load_matrix_sync(af[i], &As[wm * 32 + i * 16][kk], SLD);
            #pragma unroll
            for (int j = 0; j < 4; j++)
                wmma::load_matrix_sync(bf[j], &Bs[wn * 64 + j * 16][kk], SLD);
            #pragma unroll
            for (int i = 0; i < 2; i++)
                #pragma unroll
                for (int j = 0; j < 4; j++)
                    wmma::mma_sync(acc[i][j], af[i], bf[j], acc[i][j]);
        }
        __syncthreads();
    }
    #pragma unroll
    for (int i = 0; i < 2; i++)
        #pragma unroll
        for (int j = 0; j < 4; j++) {
            int r = rowBase + wm * 32 + i * 16;
            int c = colBase + wn * 64 + j * 16;
            wmma::store_matrix_sync(C + (size_t)r * Nc + c, acc[i][j], Nc, wmma::mem_row_major);
        }
}

// ---------------- attention logits: one warp per (n,h), dot over 64 ch ----------------
__global__ void attn_kernel(const float* __restrict__ hw, const float* __restrict__ asr,
                            const float* __restrict__ adt,
                            float* __restrict__ alsrc, float* __restrict__ aldst) {
    int item = blockIdx.x * 8 + (threadIdx.x >> 5);  // n*HEADS + h
    if (item >= NN * HEADS) return;
    int lane = threadIdx.x & 31;
    int h = item & (HEADS - 1);
    const float2* v  = (const float2*)(hw + (size_t)item * 64);
    const float2* w1 = (const float2*)(asr + h * 64);
    const float2* w2 = (const float2*)(adt + h * 64);
    float2 vv = v[lane], a1 = w1[lane], a2 = w2[lane];
    float s1 = vv.x * a1.x + vv.y * a1.y;
    float s2 = vv.x * a2.x + vv.y * a2.y;
    for (int o = 16; o > 0; o >>= 1) {
        s1 += __shfl_xor_sync(0xffffffffu, s1, o);
        s2 += __shfl_xor_sync(0xffffffffu, s2, o);
    }
    if (lane == 0) { alsrc[item] = s1; aldst[item] = s2; }
}

// ---------------- per-layer state init ----------------
__global__ void init_kernel(float* m, float* s, float* agg, int nms, int nagg) {
    int idx = blockIdx.x * blockDim.x + threadIdx.x;
    if (idx < nagg) agg[idx] = 0.f;
    if (idx < nms) { m[idx] = __int_as_float(0xff800000); s[idx] = 0.f; }
}

// ---------------- edge passes ----------------
__global__ void edge_max_kernel(const int* __restrict__ ei, const float* __restrict__ alsrc,
                                const float* __restrict__ aldst, float* m, float* alpha, int H) {
    int idx = blockIdx.x * blockDim.x + threadIdx.x;
    if (idx >= EP * H) return;
    int e = idx / H, h = idx - e * H;
    int src, dst;
    if (e < EE) { src = ei[e]; dst = ei[EE + e]; } else { src = dst = e - EE; }
    float v = alsrc[src * H + h] + aldst[dst * H + h];
    v = v > 0.f ? v : 0.2f * v;
    alpha[idx] = v;
    atomicMaxF(&m[dst * H + h], v);
}

__global__ void edge_exp_kernel(const int* __restrict__ ei, const float* __restrict__ m,
                                float* s, float* alpha, int H) {
    int idx = blockIdx.x * blockDim.x + threadIdx.x;
    if (idx >= EP * H) return;
    int e = idx / H, h = idx - e * H;
    int dst = (e < EE) ? ei[EE + e] : e - EE;
    float ex = expf(alpha[idx] - m[dst * H + h]);
    alpha[idx] = ex;
    atomicAdd(&s[dst * H + h], ex);
}

// s[i] -> 1/s[i]
__global__ void rcp_kernel(float* s, int n) {
    int idx = blockIdx.x * blockDim.x + threadIdx.x;
    if (idx < n) s[idx] = __frcp_rn(s[idx]);
}

// ---------------- message passing (H=8, C=64): float4 + red.v4, norm fused ----------------
__global__ void msg8_kernel(const int* __restrict__ ei, const float* __restrict__ alpha,
                            const float* __restrict__ srcp, const float* __restrict__ hw,
                            float* agg) {
    int idx = blockIdx.x * blockDim.x + threadIdx.x;   // EP*128 threads
    if (idx >= EP * 128) return;
    int e = idx >> 7;
    int r = idx & 127;          // float4 index within row
    int h = r >> 4;
    int src, dst;
    if (e < EE) { src = ei[e]; dst = ei[EE + e]; } else { src = dst = e - EE; }
    float a = alpha[e * 8 + h] * srcp[dst * 8 + h];
    float4 v = *(const float4*)(hw + ((size_t)src << 9) + (r << 2));
    float* o = agg + ((size_t)dst << 9) + (r << 2);
    redAddV4(o, v.x * a, v.y * a, v.z * a, v.w * a);
}

// ---------------- epilogue: bias + exact gelu + optional residual ----------------
__global__ void epi_kernel(const float* __restrict__ agg, const float* __restrict__ bias,
                           float* h, int addRes) {
    int idx = blockIdx.x * blockDim.x + threadIdx.x;
    if (idx >= NN * HC) return;
    int j = idx & (HC - 1);
    float v = agg[idx] + bias[j];
    v = 0.5f * v * (1.0f + erff(v * 0.70710678118654752f));
    if (addRes) v += h[idx];
    h[idx] = v;
}

// ---------------- layer 3: tiny GEMM [N,512]x[3,512]^T + attn logits ----------------
__global__ void gemm3_kernel(const float* __restrict__ ln, const float* __restrict__ W,
                             const float* __restrict__ asr, const float* __restrict__ adt,
                             float* hw3, float* alsrc, float* aldst) {
    int n = blockIdx.x, t = threadIdx.x;
    const float* row = ln + (size_t)n * 512;
    float p0 = 0.f, p1 = 0.f, p2 = 0.f;
    for (int k = t; k < 512; k += 128) {
        float a = row[k];
        p0 += a * W[k];
        p1 += a * W[512 + k];
        p2 += a * W[1024 + k];
    }
    __shared__ float sh[3][4];
    for (int o = 16; o > 0; o >>= 1) {
        p0 += __shfl_down_sync(0xffffffffu, p0, o);
        p1 += __shfl_down_sync(0xffffffffu, p1, o);
        p2 += __shfl_down_sync(0xffffffffu, p2, o);
    }
    int w = t >> 5, l = t & 31;
    if (l == 0) { sh[0][w] = p0; sh[1][w] = p1; sh[2][w] = p2; }
    __syncthreads();
    if (t == 0) {
        float v0 = sh[0][0] + sh[0][1] + sh[0][2] + sh[0][3];
        float v1 = sh[1][0] + sh[1][1] + sh[1][2] + sh[1][3];
        float v2 = sh[2][0] + sh[2][1] + sh[2][2] + sh[2][3];
        hw3[n * 3 + 0] = v0; hw3[n * 3 + 1] = v1; hw3[n * 3 + 2] = v2;
        alsrc[n] = v0 * asr[0] + v1 * asr[1] + v2 * asr[2];
        aldst[n] = v0 * adt[0] + v1 * adt[1] + v2 * adt[2];
    }
}

__global__ void msg3_kernel(const int* __restrict__ ei, const float* __restrict__ alpha,
                            const float* __restrict__ srcp, const float* __restrict__ hw3,
                            float* agg) {
    int e = blockIdx.x * blockDim.x + threadIdx.x;
    if (e >= EP) return;
    int src, dst;
    if (e < EE) { src = ei[e]; dst = ei[EE + e]; } else { src = dst = e - EE; }
    float a = alpha[e] * srcp[dst];
    atomicAdd(&agg[dst * 3 + 0], hw3[src * 3 + 0] * a);
    atomicAdd(&agg[dst * 3 + 1], hw3[src * 3 + 1] * a);
    atomicAdd(&agg[dst * 3 + 2], hw3[src * 3 + 2] * a);
}

// ---------------- input residual: res = x @ res_W^T + res_b ----------------
__global__ void resid_kernel(const float* __restrict__ x, const float* __restrict__ rw,
                             const float* __restrict__ rb, float* res) {
    int n = blockIdx.x, t = threadIdx.x;   // 128 threads, ci=128
    float a = x[(size_t)n * 128 + t];
    float p0 = a * rw[t], p1 = a * rw[128 + t], p2 = a * rw[256 + t];
    __shared__ float sh[3][4];
    for (int o = 16; o > 0; o >>= 1) {
        p0 += __shfl_down_sync(0xffffffffu, p0, o);
        p1 += __shfl_down_sync(0xffffffffu, p1, o);
        p2 += __shfl_down_sync(0xffffffffu, p2, o);
    }
    int w = t >> 5, l = t & 31;
    if (l == 0) { sh[0][w] = p0; sh[1][w] = p1; sh[2][w] = p2; }
    __syncthreads();
    if (t == 0) {
        res[n * 3 + 0] = sh[0][0] + sh[0][1] + sh[0][2] + sh[0][3] + rb[0];
        res[n * 3 + 1] = sh[1][0] + sh[1][1] + sh[1][2] + sh[1][3] + rb[1];
        res[n * 3 + 2] = sh[2][0] + sh[2][1] + sh[2][2] + sh[2][3] + rb[2];
    }
}

__global__ void final_kernel(const float* __restrict__ agg, const float* __restrict__ b3,
                             const float* __restrict__ res, float* __restrict__ out) {
    int idx = blockIdx.x * blockDim.x + threadIdx.x;
    if (idx >= NN * 3) return;
    out[idx] = agg[idx] + b3[idx % 3] + res[idx];
}

// ---------------- launch ----------------
extern "C" void kernel_launch(void* const* d_in, const int* in_sizes, int n_in,
                              void* d_out, int out_size) {
    const float* x    = (const float*)d_in[0];
    const int*   ei   = (const int*)d_in[1];
    const float* resW = (const float*)d_in[2];
    const float* resb = (const float*)d_in[3];

    const float* lng[4];  const float* lnb[4];
    const float* Wl[4];   const float* asr[4];
    const float* adt[4];  const float* bl[4];
    for (int l = 0; l < 4; l++) {
        int base = 4 + 6 * l;
        lng[l] = (const float*)d_in[base + 0];
        lnb[l] = (const float*)d_in[base + 1];
        Wl[l]  = (const float*)d_in[base + 2];
        asr[l] = (const float*)d_in[base + 3];
        adt[l] = (const float*)d_in[base + 4];
        bl[l]  = (const float*)d_in[base + 5];
    }

    float *ln_, *hw_, *agg_, *h_, *alsrc_, *aldst_, *m_, *s_, *alpha_, *res_;
    cudaGetSymbolAddress((void**)&ln_,    g_ln);
    cudaGetSymbolAddress((void**)&hw_,    g_hw);
    cudaGetSymbolAddress((void**)&agg_,   g_agg);
    cudaGetSymbolAddress((void**)&h_,     g_h);
    cudaGetSymbolAddress((void**)&alsrc_, g_alsrc);
    cudaGetSymbolAddress((void**)&aldst_, g_aldst);
    cudaGetSymbolAddress((void**)&m_,     g_m);
    cudaGetSymbolAddress((void**)&s_,     g_s);
    cudaGetSymbolAddress((void**)&alpha_, g_alpha);
    cudaGetSymbolAddress((void**)&res_,   g_res);

    resid_kernel<<<NN, 128>>>(x, resW, resb, res_);

    for (int l = 0; l < 3; l++) {
        const float* hin = (l == 0) ? x : h_;
        int ci = (l == 0) ? CIN : HC;
        ln_kernel<<<NN, 128>>>(hin, lng[l], lnb[l], ln_, ci);
        gemm_tf32<<<dim3(HC / BN, NP / BM), 256>>>(ln_, Wl[l], hw_, NN, ci, HC);
        attn_kernel<<<NN, 256>>>(hw_, asr[l], adt[l], alsrc_, aldst_);
        init_kernel<<<(NN * HC + 255) / 256, 256>>>(m_, s_, agg_, NN * HEADS, NN * HC);
        edge_max_kernel<<<(EP * HEADS + 255) / 256, 256>>>(ei, alsrc_, aldst_, m_, alpha_, HEADS);
        edge_exp_kernel<<<(EP * HEADS + 255) / 256, 256>>>(ei, m_, s_, alpha_, HEADS);
        rcp_kernel<<<(NN * HEADS + 255) / 256, 256>>>(s_, NN * HEADS);
        msg8_kernel<<<(EP * 128 + 255) / 256, 256>>>(ei, alpha_, s_, hw_, agg_);
        epi_kernel<<<(NN * HC + 255) / 256, 256>>>(agg_, bl[l], h_, l > 0 ? 1 : 0);
    }

    // layer 3 (heads=1, co=3, no concat, no gelu)
    ln_kernel<<<NN, 128>>>(h_, lng[3], lnb[3], ln_, HC);
    gemm3_kernel<<<NN, 128>>>(ln_, Wl[3], asr[3], adt[3], hw_, alsrc_, aldst_);
    init_kernel<<<(NN * 3 + 255) / 256, 256>>>(m_, s_, agg_, NN, NN * 3);
    edge_max_kernel<<<(EP + 255) / 256, 256>>>(ei, alsrc_, aldst_, m_, alpha_, 1);
    edge_exp_kernel<<<(EP + 255) / 256, 256>>>(ei, m_, s_, alpha_, 1);
    rcp_kernel<<<(NN + 255) / 256, 256>>>(s_, NN);
    msg3_kernel<<<(EP + 255) / 256, 256>>>(ei, alpha_, s_, hw_, agg_);
    final_kernel<<<(NN * 3 + 255) / 256, 256>>>(agg_, bl[3], res_, (float*)d_out);
}

// round 4
// speedup vs baseline: 1.7223x; 1.1913x over previous
#include <cuda_runtime.h>
#include <mma.h>
#include <math.h>

using namespace nvcuda;

#define NN   50000
#define NP   50048    // padded to multiple of 128 for GEMM tile stores
#define EE   400000
#define EP   450000   // edges + self loops
#define CIN  128
#define HID  64
#define HEADS 8
#define HC   512      // HEADS*HID
#define OUTD 3

// ---------------- scratch (device globals, no allocation) ----------------
__device__ float g_ln[NP * HC];
__device__ float g_hw[NP * HC];
__device__ float g_agg[NN * HC];
__device__ float g_h[NN * HC];
__device__ float g_alsrc[NN * HEADS];
__device__ float g_aldst[NN * HEADS];
__device__ float g_s[NN * HEADS];
__device__ float g_alpha[EP * HEADS];
__device__ float g_res[NN * OUTD];

// ---------------- helpers ----------------
__device__ __forceinline__ void redAddV4(float* addr, float a, float b, float c, float d) {
    asm volatile("red.global.add.v4.f32 [%0], {%1, %2, %3, %4};"
                 :: "l"(addr), "f"(a), "f"(b), "f"(c), "f"(d) : "memory");
}

__device__ __forceinline__ void cpAsync16(unsigned dst, const void* src, int srcBytes) {
    asm volatile("cp.async.ca.shared.global [%0], [%1], 16, %2;"
                 :: "r"(dst), "l"(src), "r"(srcBytes));
}

// ---------------- LayerNorm: one block (128 thr) per row ----------------
__global__ void ln_kernel(const float* __restrict__ x, const float* __restrict__ g,
                          const float* __restrict__ b, float* __restrict__ out, int ci) {
    int n = blockIdx.x;
    const float* row = x + (size_t)n * ci;
    float s1 = 0.f, s2 = 0.f;
    for (int k = threadIdx.x; k < ci; k += 128) {
        float v = row[k];
        s1 += v; s2 += v * v;
    }
    __shared__ float sh1[4], sh2[4];
    for (int o = 16; o > 0; o >>= 1) {
        s1 += __shfl_down_sync(0xffffffffu, s1, o);
        s2 += __shfl_down_sync(0xffffffffu, s2, o);
    }
    int w = threadIdx.x >> 5, l = threadIdx.x & 31;
    if (l == 0) { sh1[w] = s1; sh2[w] = s2; }
    __syncthreads();
    if (threadIdx.x == 0) {
        float a = 0.f, c = 0.f;
        for (int i = 0; i < 4; i++) { a += sh1[i]; c += sh2[i]; }
        sh1[0] = a; sh2[0] = c;
    }
    __syncthreads();
    float inv = 1.0f / (float)ci;
    float mean = sh1[0] * inv;
    float var  = sh2[0] * inv - mean * mean;
    float rstd = rsqrtf(var + 1e-6f);
    float* orow = out + (size_t)n * ci;
    for (int k = threadIdx.x; k < ci; k += 128)
        orow[k] = (row[k] - mean) * rstd * g[k] + b[k];
}

// ---------------- tf32 GEMM, double-buffered cp.async: C = A * B^T ----------------
#define BM 128
#define BN 128
#define BK 16
#define SPAD 8
#define SLD (BK + SPAD)   // 24 floats, row stride 96B (16B aligned)

__global__ void gemm_tf32(const float* __restrict__ A, const float* __restrict__ B,
                          float* __restrict__ C, int M, int K, int Nc) {
    __shared__ __align__(16) float As[2][BM][SLD];
    __shared__ __align__(16) float Bs[2][BN][SLD];
    int tid = threadIdx.x;
    int warp = tid >> 5;
    int wm = warp >> 1;      // 0..3 -> 32-row strip
    int wn = warp & 1;       // 0..1 -> 64-col strip
    int rowBase = blockIdx.y * BM;
    int colBase = blockIdx.x * BN;

    int r = tid >> 2;            // 0..63 (+64 on second half)
    int c = (tid & 3) * 4;       // 0,4,8,12

    wmma::fragment<wmma::accumulator, 16, 16, 8, float> acc[2][4];
    #pragma unroll
    for (int i = 0; i < 2; i++)
        #pragma unroll
        for (int j = 0; j < 4; j++) wmma::fill_fragment(acc[i][j], 0.f);

    int nIter = K / BK;

    // stage loader: copies A/B 128x16 tiles into buffer s for k-chunk it
    auto loadStage = [&](int s, int it) {
        int k0 = it * BK;
        #pragma unroll
        for (int i = 0; i < 2; i++) {
            int rr = r + i * 64;
            int gr = rowBase + rr;
            unsigned da = (unsigned)__cvta_generic_to_shared(&As[s][rr][c]);
            cpAsync16(da, A + (size_t)gr * K + k0 + c, gr < M ? 16 : 0);
            unsigned db = (unsigned)__cvta_generic_to_shared(&Bs[s][rr][c]);
            cpAsync16(db, B + (size_t)(colBase + rr) * K + k0 + c, 16);
        }
        asm volatile("cp.async.commit_group;");
    };

    loadStage(0, 0);

    for (int it = 0; it < nIter; it++) {
        int buf = it & 1;
        if (it + 1 < nIter) {
            loadStage(buf ^ 1, it + 1);
            asm volatile("cp.async.wait_group 1;");
        } else {
            asm volatile("cp.async.wait_group 0;");
        }
        __syncthreads();
        #pragma unroll
        for (int kk = 0; kk < BK; kk += 8) {
            wmma::fragment<wmma::matrix_a, 16, 16, 8, wmma::precision::tf32, wmma::row_major> af[2];
            wmma::fragment<wmma::matrix_b, 16, 16, 8, wmma::precision::tf32, wmma::col_major> bf[4];
            #pragma unroll
            for (int i = 0; i < 2; i++)
                wmma::load_matrix_sync(af[i], &As[buf][wm * 32 + i * 16][kk], SLD);
            #pragma unroll
            for (int j = 0; j < 4; j++)
                wmma::load_matrix_sync(bf[j], &Bs[buf][wn * 64 + j * 16][kk], SLD);
            #pragma unroll
            for (int i = 0; i < 2; i++)
                #pragma unroll
                for (int j = 0; j < 4; j++)
                    wmma::mma_sync(acc[i][j], af[i], bf[j], acc[i][j]);
        }
        __syncthreads();
    }
    #pragma unroll
    for (int i = 0; i < 2; i++)
        #pragma unroll
        for (int j = 0; j < 4; j++) {
            int rr = rowBase + wm * 32 + i * 16;
            int cc = colBase + wn * 64 + j * 16;
            wmma::store_matrix_sync(C + (size_t)rr * Nc + cc, acc[i][j], Nc, wmma::mem_row_major);
        }
}

// ---------------- attention logits: one warp per (n,h), dot over 64 ch ----------------
__global__ void attn_kernel(const float* __restrict__ hw, const float* __restrict__ asr,
                            const float* __restrict__ adt,
                            float* __restrict__ alsrc, float* __restrict__ aldst) {
    int item = blockIdx.x * 8 + (threadIdx.x >> 5);  // n*HEADS + h
    if (item >= NN * HEADS) return;
    int lane = threadIdx.x & 31;
    int h = item & (HEADS - 1);
    const float2* v  = (const float2*)(hw + (size_t)item * 64);
    const float2* w1 = (const float2*)(asr + h * 64);
    const float2* w2 = (const float2*)(adt + h * 64);
    float2 vv = v[lane], a1 = w1[lane], a2 = w2[lane];
    float s1 = vv.x * a1.x + vv.y * a1.y;
    float s2 = vv.x * a2.x + vv.y * a2.y;
    for (int o = 16; o > 0; o >>= 1) {
        s1 += __shfl_xor_sync(0xffffffffu, s1, o);
        s2 += __shfl_xor_sync(0xffffffffu, s2, o);
    }
    if (lane == 0) { alsrc[item] = s1; aldst[item] = s2; }
}

// ---------------- per-layer state init ----------------
__global__ void init_kernel(float* s, float* agg, int nms, int nagg) {
    int idx = blockIdx.x * blockDim.x + threadIdx.x;
    if (idx < nagg) agg[idx] = 0.f;
    if (idx < nms) s[idx] = 0.f;
}

// ---------------- single edge pass: leaky+exp+segment-sum (no max shift) ----------------
__global__ void edge_soft_kernel(const int* __restrict__ ei, const float* __restrict__ alsrc,
                                 const float* __restrict__ aldst, float* s, float* alpha, int H) {
    int idx = blockIdx.x * blockDim.x + threadIdx.x;
    if (idx >= EP * H) return;
    int e = idx / H, h = idx - e * H;
    int src, dst;
    if (e < EE) { src = ei[e]; dst = ei[EE + e]; } else { src = dst = e - EE; }
    float v = alsrc[src * H + h] + aldst[dst * H + h];
    v = v > 0.f ? v : 0.2f * v;
    float ex = expf(v);
    alpha[idx] = ex;
    atomicAdd(&s[dst * H + h], ex);
}

// s[i] -> 1/s[i]
__global__ void rcp_kernel(float* s, int n) {
    int idx = blockIdx.x * blockDim.x + threadIdx.x;
    if (idx < n) s[idx] = __frcp_rn(s[idx]);
}

// ---------------- message passing (H=8, C=64): float4 + red.v4, norm fused ----------------
__global__ void msg8_kernel(const int* __restrict__ ei, const float* __restrict__ alpha,
                            const float* __restrict__ srcp, const float* __restrict__ hw,
                            float* agg) {
    int idx = blockIdx.x * blockDim.x + threadIdx.x;   // EP*128 threads
    if (idx >= EP * 128) return;
    int e = idx >> 7;
    int r = idx & 127;          // float4 index within row
    int h = r >> 4;
    int src, dst;
    if (e < EE) { src = ei[e]; dst = ei[EE + e]; } else { src = dst = e - EE; }
    float a = alpha[e * 8 + h] * srcp[dst * 8 + h];
    float4 v = *(const float4*)(hw + ((size_t)src << 9) + (r << 2));
    float* o = agg + ((size_t)dst << 9) + (r << 2);
    redAddV4(o, v.x * a, v.y * a, v.z * a, v.w * a);
}

// ---------------- epilogue: bias + exact gelu + optional residual ----------------
__global__ void epi_kernel(const float* __restrict__ agg, const float* __restrict__ bias,
                           float* h, int addRes) {
    int idx = blockIdx.x * blockDim.x + threadIdx.x;
    if (idx >= NN * HC) return;
    int j = idx & (HC - 1);
    float v = agg[idx] + bias[j];
    v = 0.5f * v * (1.0f + erff(v * 0.70710678118654752f));
    if (addRes) v += h[idx];
    h[idx] = v;
}

// ---------------- layer 3: tiny GEMM [N,512]x[3,512]^T + attn logits ----------------
__global__ void gemm3_kernel(const float* __restrict__ ln, const float* __restrict__ W,
                             const float* __restrict__ asr, const float* __restrict__ adt,
                             float* hw3, float* alsrc, float* aldst) {
    int n = blockIdx.x, t = threadIdx.x;
    const float* row = ln + (size_t)n * 512;
    float p0 = 0.f, p1 = 0.f, p2 = 0.f;
    for (int k = t; k < 512; k += 128) {
        float a = row[k];
        p0 += a * W[k];
        p1 += a * W[512 + k];
        p2 += a * W[1024 + k];
    }
    __shared__ float sh[3][4];
    for (int o = 16; o > 0; o >>= 1) {
        p0 += __shfl_down_sync(0xffffffffu, p0, o);
        p1 += __shfl_down_sync(0xffffffffu, p1, o);
        p2 += __shfl_down_sync(0xffffffffu, p2, o);
    }
    int w = t >> 5, l = t & 31;
    if (l == 0) { sh[0][w] = p0; sh[1][w] = p1; sh[2][w] = p2; }
    __syncthreads();
    if (t == 0) {
        float v0 = sh[0][0] + sh[0][1] + sh[0][2] + sh[0][3];
        float v1 = sh[1][0] + sh[1][1] + sh[1][2] + sh[1][3];
        float v2 = sh[2][0] + sh[2][1] + sh[2][2] + sh[2][3];
        hw3[n * 3 + 0] = v0; hw3[n * 3 + 1] = v1; hw3[n * 3 + 2] = v2;
        alsrc[n] = v0 * asr[0] + v1 * asr[1] + v2 * asr[2];
        aldst[n] = v0 * adt[0] + v1 * adt[1] + v2 * adt[2];
    }
}

__global__ void msg3_kernel(const int* __restrict__ ei, const float* __restrict__ alpha,
                            const float* __restrict__ srcp, const float* __restrict__ hw3,
                            float* agg) {
    int e = blockIdx.x * blockDim.x + threadIdx.x;
    if (e >= EP) return;
    int src, dst;
    if (e < EE) { src = ei[e]; dst = ei[EE + e]; } else { src = dst = e - EE; }
    float a = alpha[e] * srcp[dst];
    atomicAdd(&agg[dst * 3 + 0], hw3[src * 3 + 0] * a);
    atomicAdd(&agg[dst * 3 + 1], hw3[src * 3 + 1] * a);
    atomicAdd(&agg[dst * 3 + 2], hw3[src * 3 + 2] * a);
}

// ---------------- input residual: res = x @ res_W^T + res_b ----------------
__global__ void resid_kernel(const float* __restrict__ x, const float* __restrict__ rw,
                             const float* __restrict__ rb, float* res) {
    int n = blockIdx.x, t = threadIdx.x;   // 128 threads, ci=128
    float a = x[(size_t)n * 128 + t];
    float p0 = a * rw[t], p1 = a * rw[128 + t], p2 = a * rw[256 + t];
    __shared__ float sh[3][4];
    for (int o = 16; o > 0; o >>= 1) {
        p0 += __shfl_down_sync(0xffffffffu, p0, o);
        p1 += __shfl_down_sync(0xffffffffu, p1, o);
        p2 += __shfl_down_sync(0xffffffffu, p2, o);
    }
    int w = t >> 5, l = t & 31;
    if (l == 0) { sh[0][w] = p0; sh[1][w] = p1; sh[2][w] = p2; }
    __syncthreads();
    if (t == 0) {
        res[n * 3 + 0] = sh[0][0] + sh[0][1] + sh[0][2] + sh[0][3] + rb[0];
        res[n * 3 + 1] = sh[1][0] + sh[1][1] + sh[1][2] + sh[1][3] + rb[1];
        res[n * 3 + 2] = sh[2][0] + sh[2][1] + sh[2][2] + sh[2][3] + rb[2];
    }
}

__global__ void final_kernel(const float* __restrict__ agg, const float* __restrict__ b3,
                             const float* __restrict__ res, float* __restrict__ out) {
    int idx = blockIdx.x * blockDim.x + threadIdx.x;
    if (idx >= NN * 3) return;
    out[idx] = agg[idx] + b3[idx % 3] + res[idx];
}

// ---------------- launch ----------------
extern "C" void kernel_launch(void* const* d_in, const int* in_sizes, int n_in,
                              void* d_out, int out_size) {
    const float* x    = (const float*)d_in[0];
    const int*   ei   = (const int*)d_in[1];
    const float* resW = (const float*)d_in[2];
    const float* resb = (const float*)d_in[3];

    const float* lng[4];  const float* lnb[4];
    const float* Wl[4];   const float* asr[4];
    const float* adt[4];  const float* bl[4];
    for (int l = 0; l < 4; l++) {
        int base = 4 + 6 * l;
        lng[l] = (const float*)d_in[base + 0];
        lnb[l] = (const float*)d_in[base + 1];
        Wl[l]  = (const float*)d_in[base + 2];
        asr[l] = (const float*)d_in[base + 3];
        adt[l] = (const float*)d_in[base + 4];
        bl[l]  = (const float*)d_in[base + 5];
    }

    float *ln_, *hw_, *agg_, *h_, *alsrc_, *aldst_, *s_, *alpha_, *res_;
    cudaGetSymbolAddress((void**)&ln_,    g_ln);
    cudaGetSymbolAddress((void**)&hw_,    g_hw);
    cudaGetSymbolAddress((void**)&agg_,   g_agg);
    cudaGetSymbolAddress((void**)&h_,     g_h);
    cudaGetSymbolAddress((void**)&alsrc_, g_alsrc);
    cudaGetSymbolAddress((void**)&aldst_, g_aldst);
    cudaGetSymbolAddress((void**)&s_,     g_s);
    cudaGetSymbolAddress((void**)&alpha_, g_alpha);
    cudaGetSymbolAddress((void**)&res_,   g_res);

    resid_kernel<<<NN, 128>>>(x, resW, resb, res_);

    for (int l = 0; l < 3; l++) {
        const float* hin = (l == 0) ? x : h_;
        int ci = (l == 0) ? CIN : HC;
        ln_kernel<<<NN, 128>>>(hin, lng[l], lnb[l], ln_, ci);
        gemm_tf32<<<dim3(HC / BN, NP / BM), 256>>>(ln_, Wl[l], hw_, NN, ci, HC);
        attn_kernel<<<NN, 256>>>(hw_, asr[l], adt[l], alsrc_, aldst_);
        init_kernel<<<(NN * HC + 255) / 256, 256>>>(s_, agg_, NN * HEADS, NN * HC);
        edge_soft_kernel<<<(EP * HEADS + 255) / 256, 256>>>(ei, alsrc_, aldst_, s_, alpha_, HEADS);
        rcp_kernel<<<(NN * HEADS + 255) / 256, 256>>>(s_, NN * HEADS);
        msg8_kernel<<<(EP * 128 + 255) / 256, 256>>>(ei, alpha_, s_, hw_, agg_);
        epi_kernel<<<(NN * HC + 255) / 256, 256>>>(agg_, bl[l], h_, l > 0 ? 1 : 0);
    }

    // layer 3 (heads=1, co=3, no concat, no gelu)
    ln_kernel<<<NN, 128>>>(h_, lng[3], lnb[3], ln_, HC);
    gemm3_kernel<<<NN, 128>>>(ln_, Wl[3], asr[3], adt[3], hw_, alsrc_, aldst_);
    init_kernel<<<(NN * 3 + 255) / 256, 256>>>(s_, agg_, NN, NN * 3);
    edge_soft_kernel<<<(EP + 255) / 256, 256>>>(ei, alsrc_, aldst_, s_, alpha_, 1);
    rcp_kernel<<<(NN + 255) / 256, 256>>>(s_, NN);
    msg3_kernel<<<(EP + 255) / 256, 256>>>(ei, alpha_, s_, hw_, agg_);
    final_kernel<<<(NN * 3 + 255) / 256, 256>>>(agg_, bl[3], res_, (float*)d_out);
}

// round 5
// speedup vs baseline: 2.8118x; 1.6326x over previous
#include <cuda_runtime.h>
#include <mma.h>
#include <math.h>

using namespace nvcuda;

#define NN   50000
#define NP   50048    // padded to multiple of 128 for GEMM tile stores
#define EE   400000
#define EP   450000   // edges + self loops
#define CIN  128
#define HID  64
#define HEADS 8
#define HC   512      // HEADS*HID
#define OUTD 3

// ---------------- scratch (device globals, no allocation) ----------------
__device__ float g_ln[NP * HC];
__device__ float g_hw[NP * HC];
__device__ float g_h[NN * HC];
__device__ float g_alsrc[NN * HEADS];
__device__ float g_aldst[NN * HEADS];
__device__ float g_sinv[NN * HEADS];
__device__ float g_alpha[EP * HEADS];   // CSR order
__device__ float g_res[NN * OUTD];
__device__ int   g_deg[NN];
__device__ int   g_rowptr[NN + 1];
__device__ int   g_cursor[NN];
__device__ int   g_csrc[EP];

// ---------------- helpers ----------------
__device__ __forceinline__ void cpAsync16(unsigned dst, const void* src, int srcBytes) {
    asm volatile("cp.async.ca.shared.global [%0], [%1], 16, %2;"
                 :: "r"(dst), "l"(src), "r"(srcBytes));
}

__device__ __forceinline__ float gelu(float v) {
    return 0.5f * v * (1.0f + erff(v * 0.70710678118654752f));
}

// ---------------- CSR build ----------------
__global__ void zero_deg_kernel(int* deg) {
    int i = blockIdx.x * blockDim.x + threadIdx.x;
    if (i < NN) deg[i] = 0;
}

__global__ void deg_kernel(const int* __restrict__ ei, int* deg) {
    int e = blockIdx.x * blockDim.x + threadIdx.x;
    if (e >= EP) return;
    int dst = (e < EE) ? ei[EE + e] : e - EE;
    atomicAdd(&deg[dst], 1);
}

// single block of 1024 threads: exclusive scan of deg -> rowptr, copy to cursor
__global__ void scan_kernel(const int* __restrict__ deg, int* rowptr, int* cursor) {
    const int T = 1024;
    const int CH = (NN + T - 1) / T;   // 49
    int t = threadIdx.x;
    int base = t * CH;
    int s = 0;
    for (int i = 0; i < CH; i++) {
        int j = base + i;
        if (j < NN) s += deg[j];
    }
    __shared__ int sh[T];
    sh[t] = s;
    __syncthreads();
    for (int o = 1; o < T; o <<= 1) {
        int v = (t >= o) ? sh[t - o] : 0;
        __syncthreads();
        sh[t] += v;
        __syncthreads();
    }
    int run = (t > 0) ? sh[t - 1] : 0;
    for (int i = 0; i < CH; i++) {
        int j = base + i;
        if (j < NN) { rowptr[j] = run; cursor[j] = run; run += deg[j]; }
    }
    if (t == T - 1) rowptr[NN] = run;
}

__global__ void scatter_kernel(const int* __restrict__ ei, int* cursor, int* csrc) {
    int e = blockIdx.x * blockDim.x + threadIdx.x;
    if (e >= EP) return;
    int src, dst;
    if (e < EE) { src = ei[e]; dst = ei[EE + e]; } else { src = dst = e - EE; }
    int pos = atomicAdd(&cursor[dst], 1);
    csrc[pos] = src;
}

// ---------------- LayerNorm (only for raw input x) ----------------
__global__ void ln_kernel(const float* __restrict__ x, const float* __restrict__ g,
                          const float* __restrict__ b, float* __restrict__ out, int ci) {
    int n = blockIdx.x;
    const float* row = x + (size_t)n * ci;
    float s1 = 0.f, s2 = 0.f;
    for (int k = threadIdx.x; k < ci; k += 128) {
        float v = row[k];
        s1 += v; s2 += v * v;
    }
    __shared__ float sh1[4], sh2[4];
    for (int o = 16; o > 0; o >>= 1) {
        s1 += __shfl_down_sync(0xffffffffu, s1, o);
        s2 += __shfl_down_sync(0xffffffffu, s2, o);
    }
    int w = threadIdx.x >> 5, l = threadIdx.x & 31;
    if (l == 0) { sh1[w] = s1; sh2[w] = s2; }
    __syncthreads();
    if (threadIdx.x == 0) {
        float a = 0.f, c = 0.f;
        for (int i = 0; i < 4; i++) { a += sh1[i]; c += sh2[i]; }
        sh1[0] = a; sh2[0] = c;
    }
    __syncthreads();
    float inv = 1.0f / (float)ci;
    float mean = sh1[0] * inv;
    float var  = sh2[0] * inv - mean * mean;
    float rstd = rsqrtf(var + 1e-6f);
    float* orow = out + (size_t)n * ci;
    for (int k = threadIdx.x; k < ci; k += 128)
        orow[k] = (row[k] - mean) * rstd * g[k] + b[k];
}

// ---------------- tf32 GEMM, double-buffered cp.async: C = A * B^T ----------------
#define BM 128
#define BN 128
#define BK 16
#define SPAD 8
#define SLD (BK + SPAD)

__global__ void gemm_tf32(const float* __restrict__ A, const float* __restrict__ B,
                          float* __restrict__ C, int M, int K, int Nc) {
    __shared__ __align__(16) float As[2][BM][SLD];
    __shared__ __align__(16) float Bs[2][BN][SLD];
    int tid = threadIdx.x;
    int warp = tid >> 5;
    int wm = warp >> 1;
    int wn = warp & 1;
    int rowBase = blockIdx.y * BM;
    int colBase = blockIdx.x * BN;

    int r = tid >> 2;
    int c = (tid & 3) * 4;

    wmma::fragment<wmma::accumulator, 16, 16, 8, float> acc[2][4];
    #pragma unroll
    for (int i = 0; i < 2; i++)
        #pragma unroll
        for (int j = 0; j < 4; j++) wmma::fill_fragment(acc[i][j], 0.f);

    int nIter = K / BK;

    auto loadStage = [&](int s, int it) {
        int k0 = it * BK;
        #pragma unroll
        for (int i = 0; i < 2; i++) {
            int rr = r + i * 64;
            int gr = rowBase + rr;
            unsigned da = (unsigned)__cvta_generic_to_shared(&As[s][rr][c]);
            cpAsync16(da, A + (size_t)gr * K + k0 + c, gr < M ? 16 : 0);
            unsigned db = (unsigned)__cvta_generic_to_shared(&Bs[s][rr][c]);
            cpAsync16(db, B + (size_t)(colBase + rr) * K + k0 + c, 16);
        }
        asm volatile("cp.async.commit_group;");
    };

    loadStage(0, 0);

    for (int it = 0; it < nIter; it++) {
        int buf = it & 1;
        if (it + 1 < nIter) {
            loadStage(buf ^ 1, it + 1);
            asm volatile("cp.async.wait_group 1;");
        } else {
            asm volatile("cp.async.wait_group 0;");
        }
        __syncthreads();
        #pragma unroll
        for (int kk = 0; kk < BK; kk += 8) {
            wmma::fragment<wmma::matrix_a, 16, 16, 8, wmma::precision::tf32, wmma::row_major> af[2];
            wmma::fragment<wmma::matrix_b, 16, 16, 8, wmma::precision::tf32, wmma::col_major> bf[4];
            #pragma unroll
            for (int i = 0; i < 2; i++)
                wmma::load_matrix_sync(af[i], &As[buf][wm * 32 + i * 16][kk], SLD);
            #pragma unroll
            for (int j = 0; j < 4; j++)
                wmma::load_matrix_sync(bf[j], &Bs[buf][wn * 64 + j * 16][kk], SLD);
            #pragma unroll
            for (int i = 0; i < 2; i++)
                #pragma unroll
                for (int j = 0; j < 4; j++)
                    wmma::mma_sync(acc[i][j], af[i], bf[j], acc[i][j]);
        }
        __syncthreads();
    }
    #pragma unroll
    for (int i = 0; i < 2; i++)
        #pragma unroll
        for (int j = 0; j < 4; j++) {
            int rr = rowBase + wm * 32 + i * 16;
            int cc = colBase + wn * 64 + j * 16;
            wmma::store_matrix_sync(C + (size_t)rr * Nc + cc, acc[i][j], Nc, wmma::mem_row_major);
        }
}

// ---------------- attention logits: one warp per (n,h) ----------------
__global__ void attn_kernel(const float* __restrict__ hw, const float* __restrict__ asr,
                            const float* __restrict__ adt,
                            float* __restrict__ alsrc, float* __restrict__ aldst) {
    int item = blockIdx.x * 8 + (threadIdx.x >> 5);
    if (item >= NN * HEADS) return;
    int lane = threadIdx.x & 31;
    int h = item & (HEADS - 1);
    const float2* v  = (const float2*)(hw + (size_t)item * 64);
    const float2* w1 = (const float2*)(asr + h * 64);
    const float2* w2 = (const float2*)(adt + h * 64);
    float2 vv = v[lane], a1 = w1[lane], a2 = w2[lane];
    float s1 = vv.x * a1.x + vv.y * a1.y;
    float s2 = vv.x * a2.x + vv.y * a2.y;
    for (int o = 16; o > 0; o >>= 1) {
        s1 += __shfl_xor_sync(0xffffffffu, s1, o);
        s2 += __shfl_xor_sync(0xffffffffu, s2, o);
    }
    if (lane == 0) { alsrc[item] = s1; aldst[item] = s2; }
}

// ---------------- gather softmax (H=8): one thread per (dst, h) ----------------
__global__ void soft8_kernel(const int* __restrict__ rp, const int* __restrict__ csrc,
                             const float* __restrict__ alsrc, const float* __restrict__ aldst,
                             float* __restrict__ alpha, float* __restrict__ sinv) {
    int idx = blockIdx.x * blockDim.x + threadIdx.x;
    if (idx >= NN * HEADS) return;
    int dst = idx >> 3, h = idx & 7;
    int s0 = rp[dst], s1 = rp[dst + 1];
    float ad = aldst[idx];
    float sum = 0.f;
    for (int i = s0; i < s1; i++) {
        int src = __ldg(&csrc[i]);
        float v = __ldg(&alsrc[src * 8 + h]) + ad;
        v = v > 0.f ? v : 0.2f * v;
        float ex = expf(v);
        alpha[i * 8 + h] = ex;
        sum += ex;
    }
    sinv[idx] = __frcp_rn(sum);
}

// ---------------- gather softmax (H=1) ----------------
__global__ void soft1_kernel(const int* __restrict__ rp, const int* __restrict__ csrc,
                             const float* __restrict__ alsrc, const float* __restrict__ aldst,
                             float* __restrict__ alpha, float* __restrict__ sinv) {
    int dst = blockIdx.x * blockDim.x + threadIdx.x;
    if (dst >= NN) return;
    int s0 = rp[dst], s1 = rp[dst + 1];
    float ad = aldst[dst];
    float sum = 0.f;
    for (int i = s0; i < s1; i++) {
        int src = __ldg(&csrc[i]);
        float v = __ldg(&alsrc[src]) + ad;
        v = v > 0.f ? v : 0.2f * v;
        float ex = expf(v);
        alpha[i] = ex;
        sum += ex;
    }
    sinv[dst] = __frcp_rn(sum);
}

// ---------------- fused gather: aggregate + bias + gelu + residual + next-LN ----------------
// block = 128 threads, one block per dst node. tid owns float4 chunk tid (4 channels).
__global__ void msgB_kernel(const int* __restrict__ rp, const int* __restrict__ csrc,
                            const float* __restrict__ alpha, const float* __restrict__ sinv,
                            const float* __restrict__ hw, const float* __restrict__ bias,
                            const float* __restrict__ lg, const float* __restrict__ lb,
                            float* __restrict__ h, float* __restrict__ lnout, int addRes) {
    int dst = blockIdx.x;
    int tid = threadIdx.x;
    int hh = tid >> 4;
    int s0 = rp[dst], s1 = rp[dst + 1];
    float siv = sinv[dst * 8 + hh];
    float4 acc = make_float4(0.f, 0.f, 0.f, 0.f);
    for (int i = s0; i < s1; i++) {
        int src = __ldg(&csrc[i]);
        float a = __ldg(&alpha[i * 8 + hh]) * siv;
        float4 v = *(const float4*)(hw + ((size_t)src << 9) + (tid << 2));
        acc.x += a * v.x; acc.y += a * v.y; acc.z += a * v.z; acc.w += a * v.w;
    }
    float4 bb = *(const float4*)(bias + (tid << 2));
    float4 r;
    r.x = gelu(acc.x + bb.x);
    r.y = gelu(acc.y + bb.y);
    r.z = gelu(acc.z + bb.z);
    r.w = gelu(acc.w + bb.w);
    float* hrow = h + ((size_t)dst << 9) + (tid << 2);
    if (addRes) {
        float4 old = *(const float4*)hrow;
        r.x += old.x; r.y += old.y; r.z += old.z; r.w += old.w;
    }
    *(float4*)hrow = r;

    // block LN over the 512 values
    float p1 = r.x + r.y + r.z + r.w;
    float p2 = r.x * r.x + r.y * r.y + r.z * r.z + r.w * r.w;
    __shared__ float sh1[4], sh2[4];
    for (int o = 16; o > 0; o >>= 1) {
        p1 += __shfl_down_sync(0xffffffffu, p1, o);
        p2 += __shfl_down_sync(0xffffffffu, p2, o);
    }
    int w = tid >> 5, l = tid & 31;
    if (l == 0) { sh1[w] = p1; sh2[w] = p2; }
    __syncthreads();
    if (tid == 0) {
        float a = sh1[0] + sh1[1] + sh1[2] + sh1[3];
        float c = sh2[0] + sh2[1] + sh2[2] + sh2[3];
        sh1[0] = a; sh2[0] = c;
    }
    __syncthreads();
    float mean = sh1[0] * (1.0f / 512.0f);
    float var  = sh2[0] * (1.0f / 512.0f) - mean * mean;
    float rstd = rsqrtf(var + 1e-6f);
    float4 gg = *(const float4*)(lg + (tid << 2));
    float4 bv = *(const float4*)(lb + (tid << 2));
    float4 o4;
    o4.x = (r.x - mean) * rstd * gg.x + bv.x;
    o4.y = (r.y - mean) * rstd * gg.y + bv.y;
    o4.z = (r.z - mean) * rstd * gg.z + bv.z;
    o4.w = (r.w - mean) * rstd * gg.w + bv.w;
    *(float4*)(lnout + ((size_t)dst << 9) + (tid << 2)) = o4;
}

// ---------------- layer 3: tiny GEMM [N,512]x[3,512]^T + attn logits ----------------
__global__ void gemm3_kernel(const float* __restrict__ ln, const float* __restrict__ W,
                             const float* __restrict__ asr, const float* __restrict__ adt,
                             float* hw3, float* alsrc, float* aldst) {
    int n = blockIdx.x, t = threadIdx.x;
    const float* row = ln + (size_t)n * 512;
    float p0 = 0.f, p1 = 0.f, p2 = 0.f;
    for (int k = t; k < 512; k += 128) {
        float a = row[k];
        p0 += a * W[k];
        p1 += a * W[512 + k];
        p2 += a * W[1024 + k];
    }
    __shared__ float sh[3][4];
    for (int o = 16; o > 0; o >>= 1) {
        p0 += __shfl_down_sync(0xffffffffu, p0, o);
        p1 += __shfl_down_sync(0xffffffffu, p1, o);
        p2 += __shfl_down_sync(0xffffffffu, p2, o);
    }
    int w = t >> 5, l = t & 31;
    if (l == 0) { sh[0][w] = p0; sh[1][w] = p1; sh[2][w] = p2; }
    __syncthreads();
    if (t == 0) {
        float v0 = sh[0][0] + sh[0][1] + sh[0][2] + sh[0][3];
        float v1 = sh[1][0] + sh[1][1] + sh[1][2] + sh[1][3];
        float v2 = sh[2][0] + sh[2][1] + sh[2][2] + sh[2][3];
        hw3[n * 3 + 0] = v0; hw3[n * 3 + 1] = v1; hw3[n * 3 + 2] = v2;
        alsrc[n] = v0 * asr[0] + v1 * asr[1] + v2 * asr[2];
        aldst[n] = v0 * adt[0] + v1 * adt[1] + v2 * adt[2];
    }
}

// ---------------- final gather: aggregate + bias + input residual -> out ----------------
__global__ void final_gather(const int* __restrict__ rp, const int* __restrict__ csrc,
                             const float* __restrict__ alpha, const float* __restrict__ sinv,
                             const float* __restrict__ hw3, const float* __restrict__ b3,
                             const float* __restrict__ res, float* __restrict__ out) {
    int dst = blockIdx.x * blockDim.x + threadIdx.x;
    if (dst >= NN) return;
    int s0 = rp[dst], s1 = rp[dst + 1];
    float siv = sinv[dst];
    float a0 = 0.f, a1 = 0.f, a2 = 0.f;
    for (int i = s0; i < s1; i++) {
        int src = __ldg(&csrc[i]);
        float a = __ldg(&alpha[i]) * siv;
        a0 += a * __ldg(&hw3[src * 3 + 0]);
        a1 += a * __ldg(&hw3[src * 3 + 1]);
        a2 += a * __ldg(&hw3[src * 3 + 2]);
    }
    out[dst * 3 + 0] = a0 + b3[0] + res[dst * 3 + 0];
    out[dst * 3 + 1] = a1 + b3[1] + res[dst * 3 + 1];
    out[dst * 3 + 2] = a2 + b3[2] + res[dst * 3 + 2];
}

// ---------------- input residual: res = x @ res_W^T + res_b ----------------
__global__ void resid_kernel(const float* __restrict__ x, const float* __restrict__ rw,
                             const float* __restrict__ rb, float* res) {
    int n = blockIdx.x, t = threadIdx.x;
    float a = x[(size_t)n * 128 + t];
    float p0 = a * rw[t], p1 = a * rw[128 + t], p2 = a * rw[256 + t];
    __shared__ float sh[3][4];
    for (int o = 16; o > 0; o >>= 1) {
        p0 += __shfl_down_sync(0xffffffffu, p0, o);
        p1 += __shfl_down_sync(0xffffffffu, p1, o);
        p2 += __shfl_down_sync(0xffffffffu, p2, o);
    }
    int w = t >> 5, l = t & 31;
    if (l == 0) { sh[0][w] = p0; sh[1][w] = p1; sh[2][w] = p2; }
    __syncthreads();
    if (t == 0) {
        res[n * 3 + 0] = sh[0][0] + sh[0][1] + sh[0][2] + sh[0][3] + rb[0];
        res[n * 3 + 1] = sh[1][0] + sh[1][1] + sh[1][2] + sh[1][3] + rb[1];
        res[n * 3 + 2] = sh[2][0] + sh[2][1] + sh[2][2] + sh[2][3] + rb[2];
    }
}

// ---------------- launch ----------------
extern "C" void kernel_launch(void* const* d_in, const int* in_sizes, int n_in,
                              void* d_out, int out_size) {
    const float* x    = (const float*)d_in[0];
    const int*   ei   = (const int*)d_in[1];
    const float* resW = (const float*)d_in[2];
    const float* resb = (const float*)d_in[3];

    const float* lng[4];  const float* lnb[4];
    const float* Wl[4];   const float* asr[4];
    const float* adt[4];  const float* bl[4];
    for (int l = 0; l < 4; l++) {
        int base = 4 + 6 * l;
        lng[l] = (const float*)d_in[base + 0];
        lnb[l] = (const float*)d_in[base + 1];
        Wl[l]  = (const float*)d_in[base + 2];
        asr[l] = (const float*)d_in[base + 3];
        adt[l] = (const float*)d_in[base + 4];
        bl[l]  = (const float*)d_in[base + 5];
    }

    float *ln_, *hw_, *h_, *alsrc_, *aldst_, *sinv_, *alpha_, *res_;
    int *deg_, *rp_, *cur_, *csrc_;
    cudaGetSymbolAddress((void**)&ln_,    g_ln);
    cudaGetSymbolAddress((void**)&hw_,    g_hw);
    cudaGetSymbolAddress((void**)&h_,     g_h);
    cudaGetSymbolAddress((void**)&alsrc_, g_alsrc);
    cudaGetSymbolAddress((void**)&aldst_, g_aldst);
    cudaGetSymbolAddress((void**)&sinv_,  g_sinv);
    cudaGetSymbolAddress((void**)&alpha_, g_alpha);
    cudaGetSymbolAddress((void**)&res_,   g_res);
    cudaGetSymbolAddress((void**)&deg_,   g_deg);
    cudaGetSymbolAddress((void**)&rp_,    g_rowptr);
    cudaGetSymbolAddress((void**)&cur_,   g_cursor);
    cudaGetSymbolAddress((void**)&csrc_,  g_csrc);

    // CSR build
    zero_deg_kernel<<<(NN + 255) / 256, 256>>>(deg_);
    deg_kernel<<<(EP + 255) / 256, 256>>>(ei, deg_);
    scan_kernel<<<1, 1024>>>(deg_, rp_, cur_);
    scatter_kernel<<<(EP + 255) / 256, 256>>>(ei, cur_, csrc_);

    resid_kernel<<<NN, 128>>>(x, resW, resb, res_);
    ln_kernel<<<NN, 128>>>(x, lng[0], lnb[0], ln_, CIN);

    for (int l = 0; l < 3; l++) {
        int ci = (l == 0) ? CIN : HC;
        gemm_tf32<<<dim3(HC / BN, NP / BM), 256>>>(ln_, Wl[l], hw_, NN, ci, HC);
        attn_kernel<<<NN, 256>>>(hw_, asr[l], adt[l], alsrc_, aldst_);
        soft8_kernel<<<(NN * HEADS + 255) / 256, 256>>>(rp_, csrc_, alsrc_, aldst_, alpha_, sinv_);
        // fused: aggregate + bias + gelu + residual + LN(params of layer l+1)
        msgB_kernel<<<NN, 128>>>(rp_, csrc_, alpha_, sinv_, hw_, bl[l],
                                 lng[l + 1], lnb[l + 1], h_, ln_, l > 0 ? 1 : 0);
    }

    // layer 3 (heads=1, co=3, no concat, no gelu)
    gemm3_kernel<<<NN, 128>>>(ln_, Wl[3], asr[3], adt[3], hw_, alsrc_, aldst_);
    soft1_kernel<<<(NN + 255) / 256, 256>>>(rp_, csrc_, alsrc_, aldst_, alpha_, sinv_);
    final_gather<<<(NN + 255) / 256, 256>>>(rp_, csrc_, alpha_, sinv_, hw_, bl[3], res_, (float*)d_out);
}